// round 2
// baseline (speedup 1.0000x reference)
#include <cuda_runtime.h>
#include <cstddef>

#define HID 4096
#define NH 32
#define NKV 8
#define DH 128
#define II 12288
#define SS 8192
#define REP (NH / NKV)
#define EPS 1e-6f

// ---------------- scratch (device globals; no allocation allowed) ----------------
__device__ float g_h[HID];        // rmsnorm(ln1) of input
__device__ float g_qkv[NH*DH + 2*NKV*DH]; // raw q (4096), k (1024), v (1024)
__device__ float g_q[NH*DH];      // normed+roped q
__device__ float g_knew[NKV*DH];  // normed+roped k (new token)
__device__ float g_scores[NH*SS]; // attn logits -> weights
__device__ float g_attnout[NH*DH];
__device__ float g_h1[HID];
__device__ float g_h2[HID];
__device__ float g_act[II];

// ---------------- utility ----------------
__global__ void zero_kernel(float* p, int n) {
    int i = blockIdx.x * blockDim.x + threadIdx.x;
    if (i < n) p[i] = 0.f;
}

// ---------------- RMSNorm over n (single block, 256 threads) ----------------
__global__ void rmsnorm_kernel(const float* __restrict__ x, const float* __restrict__ w,
                               float* __restrict__ out, int n) {
    __shared__ float red[8];
    __shared__ float s_inv;
    float ss = 0.f;
    for (int i = threadIdx.x; i < n; i += 256) { float v = x[i]; ss += v * v; }
    for (int o = 16; o; o >>= 1) ss += __shfl_xor_sync(0xffffffffu, ss, o);
    int warp = threadIdx.x >> 5, lane = threadIdx.x & 31;
    if (lane == 0) red[warp] = ss;
    __syncthreads();
    if (threadIdx.x == 0) {
        float t = 0.f;
        #pragma unroll
        for (int i = 0; i < 8; i++) t += red[i];
        s_inv = rsqrtf(t / (float)n + EPS);
    }
    __syncthreads();
    float inv = s_inv;
    for (int i = threadIdx.x; i < n; i += 256) out[i] = x[i] * inv * w[i];
}

// ---------------- generic GEMV: y[row] = W[row,:]·x (+ addv[row]) ----------------
// block per row, 256 threads, float4 streaming.
__global__ void gemv_kernel(const float* __restrict__ W, const float* __restrict__ x,
                            const float* __restrict__ addv, float* __restrict__ y, int cols) {
    int row = blockIdx.x;
    const float4* Wr = (const float4*)(W + (size_t)row * cols);
    const float4* x4 = (const float4*)x;
    int n4 = cols >> 2;
    float sum = 0.f;
    for (int i = threadIdx.x; i < n4; i += 256) {
        float4 w = Wr[i];
        float4 v = __ldg(&x4[i]);
        sum += w.x * v.x + w.y * v.y + w.z * v.z + w.w * v.w;
    }
    for (int o = 16; o; o >>= 1) sum += __shfl_xor_sync(0xffffffffu, sum, o);
    __shared__ float red[8];
    int warp = threadIdx.x >> 5, lane = threadIdx.x & 31;
    if (lane == 0) red[warp] = sum;
    __syncthreads();
    if (threadIdx.x == 0) {
        float t = 0.f;
        #pragma unroll
        for (int i = 0; i < 8; i++) t += red[i];
        y[row] = t + (addv ? addv[row] : 0.f);
    }
}

// ---------------- fused SwiGLU GEMV: act[row] = silu(Wg[row]·x) * (Wu[row]·x) ----------------
__global__ void gemv_glu_kernel(const float* __restrict__ Wg, const float* __restrict__ Wu,
                                const float* __restrict__ x, float* __restrict__ act, int cols) {
    int row = blockIdx.x;
    const float4* g4 = (const float4*)(Wg + (size_t)row * cols);
    const float4* u4 = (const float4*)(Wu + (size_t)row * cols);
    const float4* x4 = (const float4*)x;
    int n4 = cols >> 2;
    float sg = 0.f, su = 0.f;
    for (int i = threadIdx.x; i < n4; i += 256) {
        float4 v = __ldg(&x4[i]);
        float4 a = g4[i];
        float4 b = u4[i];
        sg += a.x * v.x + a.y * v.y + a.z * v.z + a.w * v.w;
        su += b.x * v.x + b.y * v.y + b.z * v.z + b.w * v.w;
    }
    for (int o = 16; o; o >>= 1) {
        sg += __shfl_xor_sync(0xffffffffu, sg, o);
        su += __shfl_xor_sync(0xffffffffu, su, o);
    }
    __shared__ float redg[8], redu[8];
    int warp = threadIdx.x >> 5, lane = threadIdx.x & 31;
    if (lane == 0) { redg[warp] = sg; redu[warp] = su; }
    __syncthreads();
    if (threadIdx.x == 0) {
        float tg = 0.f, tu = 0.f;
        #pragma unroll
        for (int i = 0; i < 8; i++) { tg += redg[i]; tu += redu[i]; }
        float s = tg / (1.f + expf(-tg));
        act[row] = s * tu;
    }
}

// ---------------- per-head RMSNorm + RoPE for q (32 heads) and k (8 heads) ----------------
// grid = 40 blocks of 128 threads. v needs no processing (lives in g_qkv).
__global__ void rope_kernel(const float* __restrict__ qkv, const float* __restrict__ cosv,
                            const float* __restrict__ sinv, const float* __restrict__ qw,
                            const float* __restrict__ kw, float* __restrict__ qout,
                            float* __restrict__ kout) {
    int h = blockIdx.x, t = threadIdx.x;
    const float* src; float* dst; const float* w;
    if (h < NH) { src = qkv + h * DH; dst = qout + h * DH; w = qw; }
    else        { src = qkv + NH * DH + (h - NH) * DH; dst = kout + (h - NH) * DH; w = kw; }
    float v = src[t];
    float ss = v * v;
    for (int o = 16; o; o >>= 1) ss += __shfl_xor_sync(0xffffffffu, ss, o);
    __shared__ float red[4];
    __shared__ float s_inv;
    __shared__ float sh[DH];
    if ((t & 31) == 0) red[t >> 5] = ss;
    __syncthreads();
    if (t == 0) s_inv = rsqrtf((red[0] + red[1] + red[2] + red[3]) * (1.f / DH) + EPS);
    __syncthreads();
    float xn = v * s_inv * w[t];
    sh[t] = xn;
    __syncthreads();
    float rot = (t < DH / 2) ? -sh[t + DH / 2] : sh[t - DH / 2];
    dst[t] = xn * cosv[t] + rot * sinv[t];
}

// ---------------- fused: copy K cache (+ new token) to out_k, compute scores ----------------
// grid (S/64, NKV), 256 threads = 8 warps; each warp handles one s-row per iter (8 iters).
__global__ void score_kernel(const float* __restrict__ k_cache, const float* __restrict__ knew,
                             const float* __restrict__ q, const float* __restrict__ position,
                             float* __restrict__ out_k, float* __restrict__ scores) {
    int hk = blockIdx.y;
    int s0 = blockIdx.x * 64;
    int warp = threadIdx.x >> 5, lane = threadIdx.x & 31;
    int pos = (int)__ldg(position);
    __shared__ float qs[REP][DH];
    for (int i = threadIdx.x; i < REP * DH; i += 256)
        qs[i >> 7][i & 127] = q[(hk * REP + (i >> 7)) * DH + (i & 127)];
    __syncthreads();
    const float scale = 0.08838834764831845f; // 128^-0.5
    #pragma unroll
    for (int it = 0; it < 8; it++) {
        int s = s0 + it * 8 + warp;
        const float* krow = (s == pos) ? (knew + hk * DH)
                                       : (k_cache + ((size_t)hk * SS + s) * DH);
        float4 kv = ((const float4*)krow)[lane];
        ((float4*)(out_k + ((size_t)hk * SS + s) * DH))[lane] = kv;
        float mask = (s > pos) ? -10000.f : 0.f;
        #pragma unroll
        for (int hh = 0; hh < REP; hh++) {
            float4 qv = ((const float4*)qs[hh])[lane];
            float d = kv.x * qv.x + kv.y * qv.y + kv.z * qv.z + kv.w * qv.w;
            for (int o = 16; o; o >>= 1) d += __shfl_xor_sync(0xffffffffu, d, o);
            if (lane == 0) scores[(size_t)(hk * REP + hh) * SS + s] = d * scale + mask;
        }
    }
}

// ---------------- softmax per head (32 blocks, row staged in SMEM) ----------------
__global__ void softmax_kernel(float* __restrict__ scores) {
    __shared__ float buf[SS];
    __shared__ float red[8];
    __shared__ float s_max, s_inv;
    int h = blockIdx.x;
    float* row = scores + (size_t)h * SS;
    int warp = threadIdx.x >> 5, lane = threadIdx.x & 31;
    float m = -1e30f;
    for (int i = threadIdx.x; i < SS; i += 256) { float v = row[i]; buf[i] = v; m = fmaxf(m, v); }
    for (int o = 16; o; o >>= 1) m = fmaxf(m, __shfl_xor_sync(0xffffffffu, m, o));
    if (lane == 0) red[warp] = m;
    __syncthreads();
    if (threadIdx.x == 0) {
        float t = red[0];
        #pragma unroll
        for (int i = 1; i < 8; i++) t = fmaxf(t, red[i]);
        s_max = t;
    }
    __syncthreads();
    float mx = s_max;
    float sum = 0.f;
    for (int i = threadIdx.x; i < SS; i += 256) { float e = expf(buf[i] - mx); buf[i] = e; sum += e; }
    for (int o = 16; o; o >>= 1) sum += __shfl_xor_sync(0xffffffffu, sum, o);
    __syncthreads(); // protect red[] reuse
    if (lane == 0) red[warp] = sum;
    __syncthreads();
    if (threadIdx.x == 0) {
        float t = 0.f;
        #pragma unroll
        for (int i = 0; i < 8; i++) t += red[i];
        s_inv = 1.f / t;
    }
    __syncthreads();
    float inv = s_inv;
    for (int i = threadIdx.x; i < SS; i += 256) row[i] = buf[i] * inv;
}

// ---------------- fused: copy V cache (+ new token) to out_v, accumulate attn·V ----------------
// grid (S/64, NKV), 256 threads = 8 warps.
__global__ void av_kernel(const float* __restrict__ v_cache, const float* __restrict__ vnew,
                          const float* __restrict__ attn, const float* __restrict__ position,
                          float* __restrict__ out_v, float* __restrict__ attnout) {
    int hk = blockIdx.y;
    int s0 = blockIdx.x * 64;
    int warp = threadIdx.x >> 5, lane = threadIdx.x & 31;
    int pos = (int)__ldg(position);
    float4 acc[REP];
    #pragma unroll
    for (int hh = 0; hh < REP; hh++) acc[hh] = make_float4(0.f, 0.f, 0.f, 0.f);
    #pragma unroll
    for (int it = 0; it < 8; it++) {
        int s = s0 + it * 8 + warp;
        const float* vrow = (s == pos) ? (vnew + hk * DH)
                                       : (v_cache + ((size_t)hk * SS + s) * DH);
        float4 vv = ((const float4*)vrow)[lane];
        ((float4*)(out_v + ((size_t)hk * SS + s) * DH))[lane] = vv;
        #pragma unroll
        for (int hh = 0; hh < REP; hh++) {
            float a = __ldg(&attn[(size_t)(hk * REP + hh) * SS + s]);
            acc[hh].x += a * vv.x; acc[hh].y += a * vv.y;
            acc[hh].z += a * vv.z; acc[hh].w += a * vv.w;
        }
    }
    __shared__ float sh[8][REP * DH]; // 16 KB
    #pragma unroll
    for (int hh = 0; hh < REP; hh++)
        ((float4*)&sh[warp][hh * DH])[lane] = acc[hh];
    __syncthreads();
    for (int i = threadIdx.x; i < REP * DH; i += 256) {
        float s = 0.f;
        #pragma unroll
        for (int w = 0; w < 8; w++) s += sh[w][i];
        atomicAdd(&attnout[(hk * REP + (i >> 7)) * DH + (i & 127)], s);
    }
}

// ---------------- host ----------------
extern "C" void kernel_launch(void* const* d_in, const int* in_sizes, int n_in,
                              void* d_out, int out_size) {
    const float* x        = (const float*)d_in[0];   // hidden_conv (4096)
    const float* position = (const float*)d_in[1];
    const float* cosv     = (const float*)d_in[2];
    const float* sinv     = (const float*)d_in[3];
    const float* k_cache  = (const float*)d_in[4];
    const float* v_cache  = (const float*)d_in[5];
    const float* Wq       = (const float*)d_in[6];
    const float* Wk       = (const float*)d_in[7];
    const float* Wv       = (const float*)d_in[8];
    const float* Wo       = (const float*)d_in[9];
    const float* Wg       = (const float*)d_in[10];
    const float* Wu       = (const float*)d_in[11];
    const float* Wd       = (const float*)d_in[12];
    const float* q_norm_w = (const float*)d_in[13];
    const float* k_norm_w = (const float*)d_in[14];
    const float* ln1_w    = (const float*)d_in[15];
    const float* ln2_w    = (const float*)d_in[16];

    float* out     = (float*)d_out;
    float* out_hid = out;
    float* out_k   = out + HID;
    float* out_v   = out + HID + (size_t)NKV * SS * DH;

    float *p_h, *p_qkv, *p_q, *p_knew, *p_scores, *p_attnout, *p_h1, *p_h2, *p_act;
    cudaGetSymbolAddress((void**)&p_h, g_h);
    cudaGetSymbolAddress((void**)&p_qkv, g_qkv);
    cudaGetSymbolAddress((void**)&p_q, g_q);
    cudaGetSymbolAddress((void**)&p_knew, g_knew);
    cudaGetSymbolAddress((void**)&p_scores, g_scores);
    cudaGetSymbolAddress((void**)&p_attnout, g_attnout);
    cudaGetSymbolAddress((void**)&p_h1, g_h1);
    cudaGetSymbolAddress((void**)&p_h2, g_h2);
    cudaGetSymbolAddress((void**)&p_act, g_act);

    zero_kernel<<<(NH * DH + 255) / 256, 256>>>(p_attnout, NH * DH);
    rmsnorm_kernel<<<1, 256>>>(x, ln1_w, p_h, HID);
    gemv_kernel<<<NH * DH, 256>>>(Wq, p_h, nullptr, p_qkv, HID);
    gemv_kernel<<<NKV * DH, 256>>>(Wk, p_h, nullptr, p_qkv + NH * DH, HID);
    gemv_kernel<<<NKV * DH, 256>>>(Wv, p_h, nullptr, p_qkv + NH * DH + NKV * DH, HID);
    rope_kernel<<<NH + NKV, DH>>>(p_qkv, cosv, sinv, q_norm_w, k_norm_w, p_q, p_knew);
    score_kernel<<<dim3(SS / 64, NKV), 256>>>(k_cache, p_knew, p_q, position, out_k, p_scores);
    softmax_kernel<<<NH, 256>>>(p_scores);
    av_kernel<<<dim3(SS / 64, NKV), 256>>>(v_cache, p_qkv + NH * DH + NKV * DH, p_scores,
                                           position, out_v, p_attnout);
    gemv_kernel<<<HID, 256>>>(Wo, p_attnout, x, p_h1, NH * DH);
    rmsnorm_kernel<<<1, 256>>>(p_h1, ln2_w, p_h2, HID);
    gemv_glu_kernel<<<II, 256>>>(Wg, Wu, p_h2, p_act, HID);
    gemv_kernel<<<HID, 256>>>(Wd, p_act, p_h1, out_hid, II);
}

// round 3
// speedup vs baseline: 1.0036x; 1.0036x over previous
#include <cuda_runtime.h>
#include <cstddef>

#define HID 4096
#define NH 32
#define NKV 8
#define DH 128
#define II 12288
#define SS 8192
#define REP (NH / NKV)
#define EPS 1e-6f

// ---------------- scratch (device globals; no allocation allowed) ----------------
__device__ float g_h[HID];
__device__ float g_qkv[NH*DH + 2*NKV*DH]; // q (4096), k (1024), v (1024)
__device__ float g_q[NH*DH];
__device__ float g_knew[NKV*DH];
__device__ float g_scores[NH*SS];
__device__ float g_attnout[NH*DH];
__device__ float g_h1[HID];
__device__ float g_h2[HID];
__device__ float g_act[II];

// ---------------- warp-level dot over a row; n4 MUST be a multiple of 128 ----------------
__device__ __forceinline__ float warp_row_dot(const float4* __restrict__ Wr,
                                              const float4* __restrict__ x4,
                                              int n4, int lane) {
    float a0 = 0.f, a1 = 0.f, a2 = 0.f, a3 = 0.f;
    #pragma unroll 1
    for (int i = lane; i < n4; i += 128) {
        float4 w0 = Wr[i];
        float4 w1 = Wr[i + 32];
        float4 w2 = Wr[i + 64];
        float4 w3 = Wr[i + 96];
        float4 v0 = __ldg(&x4[i]);
        float4 v1 = __ldg(&x4[i + 32]);
        float4 v2 = __ldg(&x4[i + 64]);
        float4 v3 = __ldg(&x4[i + 96]);
        a0 += w0.x*v0.x + w0.y*v0.y + w0.z*v0.z + w0.w*v0.w;
        a1 += w1.x*v1.x + w1.y*v1.y + w1.z*v1.z + w1.w*v1.w;
        a2 += w2.x*v2.x + w2.y*v2.y + w2.z*v2.z + w2.w*v2.w;
        a3 += w3.x*v3.x + w3.y*v3.y + w3.z*v3.z + w3.w*v3.w;
    }
    float s = (a0 + a1) + (a2 + a3);
    #pragma unroll
    for (int o = 16; o; o >>= 1) s += __shfl_xor_sync(0xffffffffu, s, o);
    return s;
}

// ---------------- RMSNorm (single block, 256 threads) + optional zero of zbuf ----------------
__global__ void rmsnorm_kernel(const float* __restrict__ x, const float* __restrict__ w,
                               float* __restrict__ out, int n,
                               float* __restrict__ zbuf, int zn) {
    if (zbuf) for (int i = threadIdx.x; i < zn; i += 256) zbuf[i] = 0.f;
    __shared__ float red[8];
    __shared__ float s_inv;
    float ss = 0.f;
    for (int i = threadIdx.x; i < n; i += 256) { float v = x[i]; ss += v * v; }
    for (int o = 16; o; o >>= 1) ss += __shfl_xor_sync(0xffffffffu, ss, o);
    int warp = threadIdx.x >> 5, lane = threadIdx.x & 31;
    if (lane == 0) red[warp] = ss;
    __syncthreads();
    if (threadIdx.x == 0) {
        float t = 0.f;
        #pragma unroll
        for (int i = 0; i < 8; i++) t += red[i];
        s_inv = rsqrtf(t / (float)n + EPS);
    }
    __syncthreads();
    float inv = s_inv;
    for (int i = threadIdx.x; i < n; i += 256) out[i] = x[i] * inv * w[i];
}

// ---------------- warp-per-row GEMV: y[row] = W[row,:]·x (+ addv[row]) ----------------
__global__ void gemv_warp_kernel(const float* __restrict__ W, const float* __restrict__ x,
                                 const float* __restrict__ addv, float* __restrict__ y,
                                 int cols, int rows) {
    int warp = threadIdx.x >> 5, lane = threadIdx.x & 31;
    int row = blockIdx.x * 8 + warp;
    if (row >= rows) return;
    const float4* Wr = (const float4*)(W + (size_t)row * cols);
    float s = warp_row_dot(Wr, (const float4*)x, cols >> 2, lane);
    if (lane == 0) y[row] = s + (addv ? addv[row] : 0.f);
}

// ---------------- merged QKV GEMV: rows [0,4096)=Wq, [4096,5120)=Wk, [5120,6144)=Wv ----------------
__global__ void qkv_gemv_kernel(const float* __restrict__ Wq, const float* __restrict__ Wk,
                                const float* __restrict__ Wv, const float* __restrict__ x,
                                float* __restrict__ y) {
    int warp = threadIdx.x >> 5, lane = threadIdx.x & 31;
    int row = blockIdx.x * 8 + warp;
    const float* W;
    int r;
    if (row < NH * DH)                 { W = Wq; r = row; }
    else if (row < NH * DH + NKV * DH) { W = Wk; r = row - NH * DH; }
    else                               { W = Wv; r = row - NH * DH - NKV * DH; }
    const float4* Wr = (const float4*)(W + (size_t)r * HID);
    float s = warp_row_dot(Wr, (const float4*)x, HID >> 2, lane);
    if (lane == 0) y[row] = s;
}

// ---------------- warp-per-row fused SwiGLU: act[row] = silu(Wg[row]·x) * (Wu[row]·x) ----------------
__global__ void glu_warp_kernel(const float* __restrict__ Wg, const float* __restrict__ Wu,
                                const float* __restrict__ x, float* __restrict__ act, int cols) {
    int warp = threadIdx.x >> 5, lane = threadIdx.x & 31;
    int row = blockIdx.x * 8 + warp;
    const float4* g4 = (const float4*)(Wg + (size_t)row * cols);
    const float4* u4 = (const float4*)(Wu + (size_t)row * cols);
    const float4* x4 = (const float4*)x;
    int n4 = cols >> 2;
    float ag0 = 0.f, ag1 = 0.f, au0 = 0.f, au1 = 0.f;
    #pragma unroll 1
    for (int i = lane; i < n4; i += 64) {
        float4 w0 = g4[i];
        float4 w1 = g4[i + 32];
        float4 u0 = u4[i];
        float4 u1 = u4[i + 32];
        float4 v0 = __ldg(&x4[i]);
        float4 v1 = __ldg(&x4[i + 32]);
        ag0 += w0.x*v0.x + w0.y*v0.y + w0.z*v0.z + w0.w*v0.w;
        ag1 += w1.x*v1.x + w1.y*v1.y + w1.z*v1.z + w1.w*v1.w;
        au0 += u0.x*v0.x + u0.y*v0.y + u0.z*v0.z + u0.w*v0.w;
        au1 += u1.x*v1.x + u1.y*v1.y + u1.z*v1.z + u1.w*v1.w;
    }
    float sg = ag0 + ag1, su = au0 + au1;
    #pragma unroll
    for (int o = 16; o; o >>= 1) {
        sg += __shfl_xor_sync(0xffffffffu, sg, o);
        su += __shfl_xor_sync(0xffffffffu, su, o);
    }
    if (lane == 0) {
        float s = sg / (1.f + expf(-sg));
        act[row] = s * su;
    }
}

// ---------------- per-head RMSNorm + RoPE ----------------
__global__ void rope_kernel(const float* __restrict__ qkv, const float* __restrict__ cosv,
                            const float* __restrict__ sinv, const float* __restrict__ qw,
                            const float* __restrict__ kw, float* __restrict__ qout,
                            float* __restrict__ kout) {
    int h = blockIdx.x, t = threadIdx.x;
    const float* src; float* dst; const float* w;
    if (h < NH) { src = qkv + h * DH; dst = qout + h * DH; w = qw; }
    else        { src = qkv + NH * DH + (h - NH) * DH; dst = kout + (h - NH) * DH; w = kw; }
    float v = src[t];
    float ss = v * v;
    for (int o = 16; o; o >>= 1) ss += __shfl_xor_sync(0xffffffffu, ss, o);
    __shared__ float red[4];
    __shared__ float s_inv;
    __shared__ float sh[DH];
    if ((t & 31) == 0) red[t >> 5] = ss;
    __syncthreads();
    if (t == 0) s_inv = rsqrtf((red[0] + red[1] + red[2] + red[3]) * (1.f / DH) + EPS);
    __syncthreads();
    float xn = v * s_inv * w[t];
    sh[t] = xn;
    __syncthreads();
    float rot = (t < DH / 2) ? -sh[t + DH / 2] : sh[t - DH / 2];
    dst[t] = xn * cosv[t] + rot * sinv[t];
}

// ---------------- fused: K-cache copy + scores ----------------
__global__ void score_kernel(const float* __restrict__ k_cache, const float* __restrict__ knew,
                             const float* __restrict__ q, const float* __restrict__ position,
                             float* __restrict__ out_k, float* __restrict__ scores) {
    int hk = blockIdx.y;
    int s0 = blockIdx.x * 64;
    int warp = threadIdx.x >> 5, lane = threadIdx.x & 31;
    int pos = (int)__ldg(position);
    __shared__ float qs[REP][DH];
    for (int i = threadIdx.x; i < REP * DH; i += 256)
        qs[i >> 7][i & 127] = q[(hk * REP + (i >> 7)) * DH + (i & 127)];
    __syncthreads();
    const float scale = 0.08838834764831845f; // 128^-0.5
    #pragma unroll
    for (int it = 0; it < 8; it++) {
        int s = s0 + it * 8 + warp;
        const float* krow = (s == pos) ? (knew + hk * DH)
                                       : (k_cache + ((size_t)hk * SS + s) * DH);
        float4 kv = ((const float4*)krow)[lane];
        ((float4*)(out_k + ((size_t)hk * SS + s) * DH))[lane] = kv;
        float mask = (s > pos) ? -10000.f : 0.f;
        #pragma unroll
        for (int hh = 0; hh < REP; hh++) {
            float4 qv = ((const float4*)qs[hh])[lane];
            float d = kv.x * qv.x + kv.y * qv.y + kv.z * qv.z + kv.w * qv.w;
            for (int o = 16; o; o >>= 1) d += __shfl_xor_sync(0xffffffffu, d, o);
            if (lane == 0) scores[(size_t)(hk * REP + hh) * SS + s] = d * scale + mask;
        }
    }
}

// ---------------- softmax per head ----------------
__global__ void softmax_kernel(float* __restrict__ scores) {
    __shared__ float buf[SS];
    __shared__ float red[8];
    __shared__ float s_max, s_inv;
    int h = blockIdx.x;
    float* row = scores + (size_t)h * SS;
    int warp = threadIdx.x >> 5, lane = threadIdx.x & 31;
    float m = -1e30f;
    for (int i = threadIdx.x; i < SS; i += 256) { float v = row[i]; buf[i] = v; m = fmaxf(m, v); }
    for (int o = 16; o; o >>= 1) m = fmaxf(m, __shfl_xor_sync(0xffffffffu, m, o));
    if (lane == 0) red[warp] = m;
    __syncthreads();
    if (threadIdx.x == 0) {
        float t = red[0];
        #pragma unroll
        for (int i = 1; i < 8; i++) t = fmaxf(t, red[i]);
        s_max = t;
    }
    __syncthreads();
    float mx = s_max;
    float sum = 0.f;
    for (int i = threadIdx.x; i < SS; i += 256) { float e = expf(buf[i] - mx); buf[i] = e; sum += e; }
    for (int o = 16; o; o >>= 1) sum += __shfl_xor_sync(0xffffffffu, sum, o);
    __syncthreads();
    if (lane == 0) red[warp] = sum;
    __syncthreads();
    if (threadIdx.x == 0) {
        float t = 0.f;
        #pragma unroll
        for (int i = 0; i < 8; i++) t += red[i];
        s_inv = 1.f / t;
    }
    __syncthreads();
    float inv = s_inv;
    for (int i = threadIdx.x; i < SS; i += 256) row[i] = buf[i] * inv;
}

// ---------------- fused: V-cache copy + attn·V ----------------
__global__ void av_kernel(const float* __restrict__ v_cache, const float* __restrict__ vnew,
                          const float* __restrict__ attn, const float* __restrict__ position,
                          float* __restrict__ out_v, float* __restrict__ attnout) {
    int hk = blockIdx.y;
    int s0 = blockIdx.x * 64;
    int warp = threadIdx.x >> 5, lane = threadIdx.x & 31;
    int pos = (int)__ldg(position);
    float4 acc[REP];
    #pragma unroll
    for (int hh = 0; hh < REP; hh++) acc[hh] = make_float4(0.f, 0.f, 0.f, 0.f);
    #pragma unroll
    for (int it = 0; it < 8; it++) {
        int s = s0 + it * 8 + warp;
        const float* vrow = (s == pos) ? (vnew + hk * DH)
                                       : (v_cache + ((size_t)hk * SS + s) * DH);
        float4 vv = ((const float4*)vrow)[lane];
        ((float4*)(out_v + ((size_t)hk * SS + s) * DH))[lane] = vv;
        #pragma unroll
        for (int hh = 0; hh < REP; hh++) {
            float a = __ldg(&attn[(size_t)(hk * REP + hh) * SS + s]);
            acc[hh].x += a * vv.x; acc[hh].y += a * vv.y;
            acc[hh].z += a * vv.z; acc[hh].w += a * vv.w;
        }
    }
    __shared__ float sh[8][REP * DH]; // 16 KB
    #pragma unroll
    for (int hh = 0; hh < REP; hh++)
        ((float4*)&sh[warp][hh * DH])[lane] = acc[hh];
    __syncthreads();
    for (int i = threadIdx.x; i < REP * DH; i += 256) {
        float s = 0.f;
        #pragma unroll
        for (int w = 0; w < 8; w++) s += sh[w][i];
        atomicAdd(&attnout[(hk * REP + (i >> 7)) * DH + (i & 127)], s);
    }
}

// ---------------- host ----------------
extern "C" void kernel_launch(void* const* d_in, const int* in_sizes, int n_in,
                              void* d_out, int out_size) {
    const float* x        = (const float*)d_in[0];
    const float* position = (const float*)d_in[1];
    const float* cosv     = (const float*)d_in[2];
    const float* sinv     = (const float*)d_in[3];
    const float* k_cache  = (const float*)d_in[4];
    const float* v_cache  = (const float*)d_in[5];
    const float* Wq       = (const float*)d_in[6];
    const float* Wk       = (const float*)d_in[7];
    const float* Wv       = (const float*)d_in[8];
    const float* Wo       = (const float*)d_in[9];
    const float* Wg       = (const float*)d_in[10];
    const float* Wu       = (const float*)d_in[11];
    const float* Wd       = (const float*)d_in[12];
    const float* q_norm_w = (const float*)d_in[13];
    const float* k_norm_w = (const float*)d_in[14];
    const float* ln1_w    = (const float*)d_in[15];
    const float* ln2_w    = (const float*)d_in[16];

    float* out     = (float*)d_out;
    float* out_hid = out;
    float* out_k   = out + HID;
    float* out_v   = out + HID + (size_t)NKV * SS * DH;

    float *p_h, *p_qkv, *p_q, *p_knew, *p_scores, *p_attnout, *p_h1, *p_h2, *p_act;
    cudaGetSymbolAddress((void**)&p_h, g_h);
    cudaGetSymbolAddress((void**)&p_qkv, g_qkv);
    cudaGetSymbolAddress((void**)&p_q, g_q);
    cudaGetSymbolAddress((void**)&p_knew, g_knew);
    cudaGetSymbolAddress((void**)&p_scores, g_scores);
    cudaGetSymbolAddress((void**)&p_attnout, g_attnout);
    cudaGetSymbolAddress((void**)&p_h1, g_h1);
    cudaGetSymbolAddress((void**)&p_h2, g_h2);
    cudaGetSymbolAddress((void**)&p_act, g_act);

    // 1. rmsnorm(ln1) + zero attnout
    rmsnorm_kernel<<<1, 256>>>(x, ln1_w, p_h, HID, p_attnout, NH * DH);
    // 2. merged QKV GEMV (6144 rows, warp-per-row)
    qkv_gemv_kernel<<<(NH * DH + 2 * NKV * DH) / 8, 256>>>(Wq, Wk, Wv, p_h, p_qkv);
    // 3. per-head norm + rope
    rope_kernel<<<NH + NKV, DH>>>(p_qkv, cosv, sinv, q_norm_w, k_norm_w, p_q, p_knew);
    // 4. K-cache copy + scores
    score_kernel<<<dim3(SS / 64, NKV), 256>>>(k_cache, p_knew, p_q, position, out_k, p_scores);
    // 5. softmax
    softmax_kernel<<<NH, 256>>>(p_scores);
    // 6. V-cache copy + attn·V
    av_kernel<<<dim3(SS / 64, NKV), 256>>>(v_cache, p_qkv + NH * DH + NKV * DH, p_scores,
                                           position, out_v, p_attnout);
    // 7. Wo GEMV + residual
    gemv_warp_kernel<<<HID / 8, 256>>>(Wo, p_attnout, x, p_h1, NH * DH, HID);
    // 8. rmsnorm(ln2)
    rmsnorm_kernel<<<1, 256>>>(p_h1, ln2_w, p_h2, HID, nullptr, 0);
    // 9. fused SwiGLU GEMV
    glu_warp_kernel<<<II / 8, 256>>>(Wg, Wu, p_h2, p_act, HID);
    // 10. Wd GEMV + residual -> out
    gemv_warp_kernel<<<HID / 8, 256>>>(Wd, p_act, p_h1, out_hid, II, HID);
}